// round 14
// baseline (speedup 1.0000x reference)
#include <cuda_runtime.h>
#include <math.h>

#define VOCAB 50000
#define E 128
#define H 128
#define B 256
#define T 2048

typedef unsigned long long ull;

// Packed f32x2 FMA (Blackwell)
#define FMA2(d, a, b, c) \
    asm("fma.rn.f32x2 %0, %1, %2, %3;" : "=l"(d) : "l"(a), "l"(b), "l"(c))
#define PACK2(d, lo, hi) \
    asm("mov.b64 %0, {%1, %2};" : "=l"(d) : "f"(lo), "f"(hi))
#define UNPACK2(lo, hi, v) \
    asm("mov.b64 {%0, %1}, %2;" : "=f"(lo), "=f"(hi) : "l"(v))

// Branchless fast tanh: tanh(x) = 1 - 2/(1 + e^{2x}) via MUFU ex2/rcp.
// rel err ~1e-6 (correct +-1 saturation), safe vs the 1e-3 gate.
__device__ __forceinline__ float fast_tanh(float x) {
    float e, r;
    asm("ex2.approx.f32 %0, %1;" : "=f"(e) : "f"(x * 2.8853900817779268f));
    asm("rcp.approx.f32 %0, %1;" : "=f"(r) : "f"(e + 1.0f));
    return 1.0f - 2.0f * r;
}
__device__ __forceinline__ float fast_sigmoid(float x) {
    float e, r;
    asm("ex2.approx.f32 %0, %1;" : "=f"(e) : "f"(-x * 1.4426950408889634f));
    asm("rcp.approx.f32 %0, %1;" : "=f"(r) : "f"(e + 1.0f));
    return r;
}

// Device scratch (sanctioned: __device__ globals, no allocation)
__device__ float g_X0[VOCAB * H];   // emb @ W_ih0 + b0 per vocab id
__device__ int   g_order[B];        // rows sorted by length, descending

// ---------------------------------------------------------------------------
// Kernel B: block 0 rank-sorts lengths, all blocks compute X0.
// ---------------------------------------------------------------------------
__global__ void __launch_bounds__(256)
x0_kernel(const float* __restrict__ emb,
          const float* __restrict__ W_ih,
          const float* __restrict__ b,
          const int* __restrict__ lengths) {
    __shared__ __align__(16) float embs[H];
    __shared__ float part[2 * H];
    __shared__ int s_len[B];

    int tid   = threadIdx.x;
    int half  = tid >> 7;
    int j     = tid & 127;
    int kbase = half * 64;

    if (blockIdx.x == 0) {
        s_len[tid] = lengths[tid];
        __syncthreads();
        int li = s_len[tid];
        int rank = 0;
        for (int jj = 0; jj < B; jj++) {
            int lj = s_len[jj];
            rank += (lj > li) || (lj == li && jj < tid);
        }
        g_order[rank] = tid;
        __syncthreads();
    }

    ull w[32];
    #pragma unroll
    for (int kk = 0; kk < 32; kk++) {
        int k = kbase + 2 * kk;
        PACK2(w[kk], W_ih[k * H + j], W_ih[(k + 1) * H + j]);
    }
    float b0 = b[j];

    for (int r = blockIdx.x; r < VOCAB; r += gridDim.x) {
        if (tid < H) embs[tid] = emb[r * E + tid];
        __syncthreads();
        ull acc = 0;
        #pragma unroll
        for (int i = 0; i < 16; i++) {
            ulonglong2 ev = *(const ulonglong2*)&embs[kbase + 4 * i];
            FMA2(acc, ev.x, w[2 * i], acc);
            FMA2(acc, ev.y, w[2 * i + 1], acc);
        }
        float lo, hi;
        UNPACK2(lo, hi, acc);
        part[tid] = lo + hi;
        __syncthreads();
        if (tid < H) g_X0[r * H + j] = b0 + part[j] + part[H + j];
        __syncthreads();
    }
}

// ---------------------------------------------------------------------------
// Kernel C: persistent per-row RNN (R4 shape; tail-overlapped step order).
// 256 CTAs (one sorted row each, longest first), 256 threads = 8 warps.
// Lane layout: warp w, lane l -> column j = 16*w + (l&15), k-half = l>>4.
// Step order (to hide shuffle/tanh latency under FMA issue):
//   1. acc0+acc1 over h0(t)  -> collapse -> shfl s0, shfl s1 (in flight)
//   2. acc2 over h1(t-1)     -> covers the shuffle latency
//   3. h0(t+1) = tanh(x0 + s0r) STS   (s0r long ready)
//   4. collapse s2 -> shfl s2 -> h1(t) = tanh(b1 + s1r + s2r) STS -> BAR
// h double-buffered -> 1 barrier/step.
// ---------------------------------------------------------------------------
__global__ void __launch_bounds__(256, 1)
rnn_kernel(const int* __restrict__ x, const int* __restrict__ lengths,
           const float* __restrict__ W_ih, const float* __restrict__ W_hh,
           const float* __restrict__ b, const float* __restrict__ cls_w,
           const float* __restrict__ cls_b, float* __restrict__ out) {
    __shared__ int xrow[T];
    __shared__ __align__(16) float h0s[2][H];
    __shared__ __align__(16) float h1s[2][H];

    int tid   = threadIdx.x;
    int warp  = tid >> 5;
    int lane  = tid & 31;
    int j     = warp * 16 + (lane & 15);
    int half  = lane >> 4;
    int kbase = half * 64;

    int row = g_order[blockIdx.x];
    int len = lengths[row];

    // Pre-packed weight k-pair columns in registers: 3 x 32 ull.
    ull w0p[32], w1p[32], w2p[32];
    #pragma unroll
    for (int kk = 0; kk < 32; kk++) {
        int k = kbase + 2 * kk;
        PACK2(w0p[kk], W_hh[k * H + j],           W_hh[(k + 1) * H + j]);           // W_hh0
        PACK2(w1p[kk], W_ih[H * H + k * H + j],   W_ih[H * H + (k + 1) * H + j]);   // W_ih1
        PACK2(w2p[kk], W_hh[H * H + k * H + j],   W_hh[H * H + (k + 1) * H + j]);   // W_hh1
    }
    float b1v = b[H + j];

    // Stage token ids for this row into smem (8 KB).
    for (int i = tid; i < T; i += 256) xrow[i] = x[row * T + i];
    __syncthreads();

    // Prologue: h0(0) = tanh(X0[tok0]) (b0 folded into X0, h_init = 0); h1(-1)=0.
    if (half == 0) h0s[0][j] = fast_tanh(g_X0[xrow[0] * H + j]);
    else           h1s[0][j] = 0.f;
    float x0cur = 0.f, x0nxt = 0.f;
    if (half == 0) x0cur = g_X0[xrow[(len > 1) ? 1 : 0] * H + j];
    __syncthreads();

    for (int t = 0; t < len; t++) {
        int p = t & 1;
        const float* hr0 = &h0s[p][kbase];
        const float* hr1 = &h1s[p][kbase];

        // Prefetch X0 for superstep t+1 (needs tok[t+2]).
        if (half == 0) {
            int tn = t + 2;
            if (tn > len - 1) tn = len - 1;
            x0nxt = g_X0[xrow[tn] * H + j];
        }

        // --- Phase 1: acc0 + acc1 over h0(t) (shared hp loads) ---
        ull acc0 = 0, acc1 = 0;
        #pragma unroll
        for (int i = 0; i < 16; i++) {
            ulonglong2 hp = *(const ulonglong2*)(hr0 + 4 * i);
            FMA2(acc0, hp.x, w0p[2 * i],     acc0);
            FMA2(acc0, hp.y, w0p[2 * i + 1], acc0);
            FMA2(acc1, hp.x, w1p[2 * i],     acc1);
            FMA2(acc1, hp.y, w1p[2 * i + 1], acc1);
        }
        float lo, hi, s0, s1;
        UNPACK2(lo, hi, acc0); s0 = lo + hi;
        UNPACK2(lo, hi, acc1); s1 = lo + hi;
        // Launch both cross-half shuffles now; latency covered by Phase 2.
        float s0r = s0 + __shfl_xor_sync(0xffffffffu, s0, 16);
        float s1r = s1 + __shfl_xor_sync(0xffffffffu, s1, 16);

        // --- Phase 2: acc2 over h1(t-1) ---
        ull acc2 = 0;
        #pragma unroll
        for (int i = 0; i < 16; i++) {
            ulonglong2 gp = *(const ulonglong2*)(hr1 + 4 * i);
            FMA2(acc2, gp.x, w2p[2 * i],     acc2);
            FMA2(acc2, gp.y, w2p[2 * i + 1], acc2);
        }

        // --- Phase 3: h0(t+1) write (mid-step; s0r ready under Phase 2) ---
        if (half == 0) h0s[p ^ 1][j] = fast_tanh(x0cur + s0r);

        // --- Phase 4: h1(t) tail ---
        float s2;
        UNPACK2(lo, hi, acc2); s2 = lo + hi;
        float s2r = s2 + __shfl_xor_sync(0xffffffffu, s2, 16);
        if (half) h1s[p ^ 1][j] = fast_tanh(b1v + s1r + s2r);
        __syncthreads();

        x0cur = x0nxt;
    }

    // ---- classifier: sigmoid(h1_final . cls_w + cls_b) ----
    const float* h1f = h1s[len & 1];
    if (tid < 32) {
        float v = 0.f;
        #pragma unroll
        for (int m = 0; m < 4; m++) {
            int jj = tid + 32 * m;
            v += h1f[jj] * cls_w[jj];
        }
        #pragma unroll
        for (int off = 16; off; off >>= 1)
            v += __shfl_xor_sync(0xffffffffu, v, off);
        if (tid == 0) out[row] = fast_sigmoid(v + cls_b[0]);
    }
}

// ---------------------------------------------------------------------------
extern "C" void kernel_launch(void* const* d_in, const int* in_sizes, int n_in,
                              void* d_out, int out_size) {
    const int*   x       = (const int*)d_in[0];
    const int*   lengths = (const int*)d_in[1];
    const float* emb     = (const float*)d_in[2];
    const float* W_ih    = (const float*)d_in[3];
    const float* W_hh    = (const float*)d_in[4];
    const float* b       = (const float*)d_in[5];
    const float* cls_w   = (const float*)d_in[6];
    const float* cls_b   = (const float*)d_in[7];
    float*       out     = (float*)d_out;

    x0_kernel<<<1024, 256>>>(emb, W_ih, b, lengths);
    rnn_kernel<<<B, 256>>>(x, lengths, W_ih, W_hh, b, cls_w, cls_b, out);
}

// round 15
// speedup vs baseline: 1.3163x; 1.3163x over previous
#include <cuda_runtime.h>
#include <math.h>

#define VOCAB 50000
#define E 128
#define H 128
#define B 256
#define T 2048

typedef unsigned long long ull;

// Packed f32x2 FMA (Blackwell)
#define FMA2(d, a, b, c) \
    asm("fma.rn.f32x2 %0, %1, %2, %3;" : "=l"(d) : "l"(a), "l"(b), "l"(c))
#define PACK2(d, lo, hi) \
    asm("mov.b64 %0, {%1, %2};" : "=l"(d) : "f"(lo), "f"(hi))
#define UNPACK2(lo, hi, v) \
    asm("mov.b64 {%0, %1}, %2;" : "=f"(lo), "=f"(hi) : "l"(v))

// Hardware tanh: single MUFU.TANH instruction (sm_75+), lat ~16 cyc.
// Max abs err ~5e-4 on the final atom; recurrence contraction keeps the
// end-to-end rel_err under the 1e-3 gate (verified by bench rel_err).
__device__ __forceinline__ float hw_tanh(float x) {
    float y;
    asm("tanh.approx.f32 %0, %1;" : "=f"(y) : "f"(x));
    return y;
}
// sigmoid(x) = 0.5 * (1 + tanh(x/2)) — one MUFU.TANH.
__device__ __forceinline__ float hw_sigmoid(float x) {
    return 0.5f * (1.0f + hw_tanh(0.5f * x));
}

// Device scratch (sanctioned: __device__ globals, no allocation)
__device__ float g_X0[VOCAB * H];   // emb @ W_ih0 + b0 per vocab id
__device__ int   g_order[B];        // rows sorted by length, descending

// ---------------------------------------------------------------------------
// Kernel B: block 0 rank-sorts lengths, all blocks compute X0.
// ---------------------------------------------------------------------------
__global__ void __launch_bounds__(256)
x0_kernel(const float* __restrict__ emb,
          const float* __restrict__ W_ih,
          const float* __restrict__ b,
          const int* __restrict__ lengths) {
    __shared__ __align__(16) float embs[H];
    __shared__ float part[2 * H];
    __shared__ int s_len[B];

    int tid   = threadIdx.x;
    int half  = tid >> 7;
    int j     = tid & 127;
    int kbase = half * 64;

    if (blockIdx.x == 0) {
        s_len[tid] = lengths[tid];
        __syncthreads();
        int li = s_len[tid];
        int rank = 0;
        for (int jj = 0; jj < B; jj++) {
            int lj = s_len[jj];
            rank += (lj > li) || (lj == li && jj < tid);
        }
        g_order[rank] = tid;
        __syncthreads();
    }

    ull w[32];
    #pragma unroll
    for (int kk = 0; kk < 32; kk++) {
        int k = kbase + 2 * kk;
        PACK2(w[kk], W_ih[k * H + j], W_ih[(k + 1) * H + j]);
    }
    float b0 = b[j];

    for (int r = blockIdx.x; r < VOCAB; r += gridDim.x) {
        if (tid < H) embs[tid] = emb[r * E + tid];
        __syncthreads();
        ull acc = 0;
        #pragma unroll
        for (int i = 0; i < 16; i++) {
            ulonglong2 ev = *(const ulonglong2*)&embs[kbase + 4 * i];
            FMA2(acc, ev.x, w[2 * i], acc);
            FMA2(acc, ev.y, w[2 * i + 1], acc);
        }
        float lo, hi;
        UNPACK2(lo, hi, acc);
        part[tid] = lo + hi;
        __syncthreads();
        if (tid < H) g_X0[r * H + j] = b0 + part[j] + part[H + j];
        __syncthreads();
    }
}

// ---------------------------------------------------------------------------
// Kernel C: persistent per-row RNN (R13 structure; MUFU.TANH activation).
// 256 CTAs (one sorted row each, longest first), 256 threads = 8 warps.
// Lane layout: warp w, lane l -> column j = 16*w + (l&15), k-half = l>>4.
// Superstep t computes BOTH h1(t) and h0(t+1) from {h0(t), h1(t-1)}:
//   h1(t)   = tanh(b1 + W_ih1 h0(t) + W_hh1 h1(t-1))
//   h0(t+1) = tanh(X0[tok(t+1)] + W_hh0 h0(t))
// Three independent FMA2 chains; s1+s2 merged after unpack (2 shuffles).
// h double-buffered -> 1 barrier/step.
// ---------------------------------------------------------------------------
__global__ void __launch_bounds__(256, 1)
rnn_kernel(const int* __restrict__ x, const int* __restrict__ lengths,
           const float* __restrict__ W_ih, const float* __restrict__ W_hh,
           const float* __restrict__ b, const float* __restrict__ cls_w,
           const float* __restrict__ cls_b, float* __restrict__ out) {
    __shared__ int xrow[T];
    __shared__ __align__(16) float h0s[2][H];
    __shared__ __align__(16) float h1s[2][H];

    int tid   = threadIdx.x;
    int warp  = tid >> 5;
    int lane  = tid & 31;
    int j     = warp * 16 + (lane & 15);
    int half  = lane >> 4;
    int kbase = half * 64;

    int row = g_order[blockIdx.x];
    int len = lengths[row];

    // Pre-packed weight k-pair columns in registers: 3 x 32 ull.
    ull w0p[32], w1p[32], w2p[32];
    #pragma unroll
    for (int kk = 0; kk < 32; kk++) {
        int k = kbase + 2 * kk;
        PACK2(w0p[kk], W_hh[k * H + j],           W_hh[(k + 1) * H + j]);           // W_hh0
        PACK2(w1p[kk], W_ih[H * H + k * H + j],   W_ih[H * H + (k + 1) * H + j]);   // W_ih1
        PACK2(w2p[kk], W_hh[H * H + k * H + j],   W_hh[H * H + (k + 1) * H + j]);   // W_hh1
    }
    float b1v = b[H + j];

    // Stage token ids for this row into smem (8 KB).
    for (int i = tid; i < T; i += 256) xrow[i] = x[row * T + i];
    __syncthreads();

    // Prologue: h0(0) = tanh(X0[tok0]) (b0 folded into X0, h_init = 0); h1(-1)=0.
    if (half == 0) h0s[0][j] = hw_tanh(g_X0[xrow[0] * H + j]);
    else           h1s[0][j] = 0.f;
    float x0cur = 0.f, x0nxt = 0.f;
    if (half == 0) x0cur = g_X0[xrow[(len > 1) ? 1 : 0] * H + j];
    __syncthreads();

    for (int t = 0; t < len; t++) {
        int p = t & 1;
        const float* hr0 = &h0s[p][kbase];
        const float* hr1 = &h1s[p][kbase];

        // Prefetch X0 for superstep t+1 (needs tok[t+2]).
        if (half == 0) {
            int tn = t + 2;
            if (tn > len - 1) tn = len - 1;
            x0nxt = g_X0[xrow[tn] * H + j];
        }

        // Three matmul partials over this k-half (FFMA2-packed, 3 chains).
        ull acc0 = 0, acc1 = 0, acc2 = 0;
        #pragma unroll
        for (int i = 0; i < 16; i++) {
            ulonglong2 hp = *(const ulonglong2*)(hr0 + 4 * i);
            FMA2(acc0, hp.x, w0p[2 * i],     acc0);
            FMA2(acc0, hp.y, w0p[2 * i + 1], acc0);
            FMA2(acc1, hp.x, w1p[2 * i],     acc1);
            FMA2(acc1, hp.y, w1p[2 * i + 1], acc1);
            ulonglong2 gp = *(const ulonglong2*)(hr1 + 4 * i);
            FMA2(acc2, gp.x, w2p[2 * i],     acc2);
            FMA2(acc2, gp.y, w2p[2 * i + 1], acc2);
        }

        // Collapse packed lanes; merge s1+s2 before the cross-half reduce.
        float lo, hi, s0, s1, s2;
        UNPACK2(lo, hi, acc0); s0 = lo + hi;
        UNPACK2(lo, hi, acc1); s1 = lo + hi;
        UNPACK2(lo, hi, acc2); s2 = lo + hi;
        float s12 = s1 + s2;
        s0  += __shfl_xor_sync(0xffffffffu, s0,  16);
        s12 += __shfl_xor_sync(0xffffffffu, s12, 16);

        // half 0 produces h0(t+1); half 1 produces h1(t).
        float argv = half ? (b1v + s12) : (x0cur + s0);
        float hv = hw_tanh(argv);

        // Double-buffered write: no WAR hazard, single barrier per step.
        float* dst = half ? &h1s[p ^ 1][0] : &h0s[p ^ 1][0];
        dst[j] = hv;
        __syncthreads();

        x0cur = x0nxt;
    }

    // ---- classifier: sigmoid(h1_final . cls_w + cls_b) ----
    const float* h1f = h1s[len & 1];
    if (tid < 32) {
        float v = 0.f;
        #pragma unroll
        for (int m = 0; m < 4; m++) {
            int jj = tid + 32 * m;
            v += h1f[jj] * cls_w[jj];
        }
        #pragma unroll
        for (int off = 16; off; off >>= 1)
            v += __shfl_xor_sync(0xffffffffu, v, off);
        if (tid == 0) out[row] = hw_sigmoid(v + cls_b[0]);
    }
}

// ---------------------------------------------------------------------------
extern "C" void kernel_launch(void* const* d_in, const int* in_sizes, int n_in,
                              void* d_out, int out_size) {
    const int*   x       = (const int*)d_in[0];
    const int*   lengths = (const int*)d_in[1];
    const float* emb     = (const float*)d_in[2];
    const float* W_ih    = (const float*)d_in[3];
    const float* W_hh    = (const float*)d_in[4];
    const float* b       = (const float*)d_in[5];
    const float* cls_w   = (const float*)d_in[6];
    const float* cls_b   = (const float*)d_in[7];
    float*       out     = (float*)d_out;

    x0_kernel<<<1024, 256>>>(emb, W_ih, b, lengths);
    rnn_kernel<<<B, 256>>>(x, lengths, W_ih, W_hh, b, cls_w, cls_b, out);
}